// round 3
// baseline (speedup 1.0000x reference)
#include <cuda_runtime.h>
#include <cuda_bf16.h>

// Node constants packed per node as 4 float4 (64B):
//   q0 = (r00, r01, r02, u0)
//   q1 = (r10, r11, r12, u1)
//   q2 = (r20, r21, r22, u2)
//   q3 = (cx,  cy,  cz,  0 )
// where u = t + c - R*c, so contribution = w * (R*p + u).
#define MAXN 4096
__device__ float4 g_node[MAXN * 4];

// ---------------------------------------------------------------------------
// Kernel 1: Rodrigues + per-node constant precompute (tiny: N=512)
// ---------------------------------------------------------------------------
__global__ void prep_kernel(const float* __restrict__ cp,
                            const float* __restrict__ rv,
                            const float* __restrict__ t,
                            int N) {
    int n = blockIdx.x * blockDim.x + threadIdx.x;
    if (n >= N) return;

    float x = rv[3 * n + 0], y = rv[3 * n + 1], z = rv[3 * n + 2];
    float th2 = x * x + y * y + z * z + 1e-12f;
    float th = sqrtf(th2);
    float s, co;
    sincosf(th, &s, &co);
    float a = s / th;            // sin(th)/th
    float b = (1.0f - co) / th2; // (1-cos(th))/th^2

    // R = I + a*skew(w) + b*skew(w)^2
    float xx = x * x, yy = y * y, zz = z * z;
    float xy = x * y, xz = x * z, yz = y * z;
    float r00 = 1.0f - b * (yy + zz);
    float r01 = -a * z + b * xy;
    float r02 =  a * y + b * xz;
    float r10 =  a * z + b * xy;
    float r11 = 1.0f - b * (xx + zz);
    float r12 = -a * x + b * yz;
    float r20 = -a * y + b * xz;
    float r21 =  a * x + b * yz;
    float r22 = 1.0f - b * (xx + yy);

    float cx = cp[3 * n + 0], cy = cp[3 * n + 1], cz = cp[3 * n + 2];
    float tx = t[3 * n + 0],  ty = t[3 * n + 1],  tz = t[3 * n + 2];

    float u0 = tx + cx - (r00 * cx + r01 * cy + r02 * cz);
    float u1 = ty + cy - (r10 * cx + r11 * cy + r12 * cz);
    float u2 = tz + cz - (r20 * cx + r21 * cy + r22 * cz);

    g_node[n * 4 + 0] = make_float4(r00, r01, r02, u0);
    g_node[n * 4 + 1] = make_float4(r10, r11, r12, u1);
    g_node[n * 4 + 2] = make_float4(r20, r21, r22, u2);
    g_node[n * 4 + 3] = make_float4(cx, cy, cz, 0.0f);
}

// ---------------------------------------------------------------------------
// Kernel 2: main P x N warp field. One thread per point, node constants
// staged in shared memory (uniform-address LDS.128 broadcast).
// ---------------------------------------------------------------------------
__global__ void __launch_bounds__(128)
warp_kernel(const float* __restrict__ pts,
            float* __restrict__ out,
            int N, int P) {
    extern __shared__ float4 sm[];
    for (int i = threadIdx.x; i < N * 4; i += blockDim.x)
        sm[i] = g_node[i];
    __syncthreads();

    int pi = blockIdx.x * blockDim.x + threadIdx.x;
    if (pi >= P) return;

    float px = pts[3 * pi + 0];
    float py = pts[3 * pi + 1];
    float pz = pts[3 * pi + 2];

    float ax = 0.0f, ay = 0.0f, az = 0.0f, S = 0.0f;

    const float kExpScale = -0.02f; // -1/(2*sigma^2) = -1/50

#pragma unroll 4
    for (int n = 0; n < N; ++n) {
        float4 q0 = sm[n * 4 + 0];
        float4 q1 = sm[n * 4 + 1];
        float4 q2 = sm[n * 4 + 2];
        float4 q3 = sm[n * 4 + 3];

        float dx = px - q3.x;
        float dy = py - q3.y;
        float dz = pz - q3.z;
        float d2 = fmaf(dx, dx, fmaf(dy, dy, dz * dz));
        float w = __expf(d2 * kExpScale);

        float y0 = fmaf(q0.x, px, fmaf(q0.y, py, fmaf(q0.z, pz, q0.w)));
        float y1 = fmaf(q1.x, px, fmaf(q1.y, py, fmaf(q1.z, pz, q1.w)));
        float y2 = fmaf(q2.x, px, fmaf(q2.y, py, fmaf(q2.z, pz, q2.w)));

        ax = fmaf(w, y0, ax);
        ay = fmaf(w, y1, ay);
        az = fmaf(w, y2, az);
        S += w;
    }

    float inv = 1.0f / (S + 1e-5f);
    out[3 * pi + 0] = ax * inv;
    out[3 * pi + 1] = ay * inv;
    out[3 * pi + 2] = az * inv;
}

// ---------------------------------------------------------------------------
// Kernel 3: edge regularizer, single block, deterministic tree reduction.
// resid = R_i (c_j - c_i) + c_i + t_i - (c_j + t_j); reg = sum |resid|^2
// NOTE: edges arrive as int32 (JAX x64 disabled downcasts int64 -> int32).
// ---------------------------------------------------------------------------
__global__ void edge_kernel(const float* __restrict__ cp,
                            const float* __restrict__ t,
                            const int* __restrict__ edges,
                            float* __restrict__ out,
                            int E, int P, int N) {
    __shared__ float red[1024];
    float acc = 0.0f;

    for (int m = threadIdx.x; m < E; m += blockDim.x) {
        int i = edges[2 * m + 0];
        int j = edges[2 * m + 1];
        // defensive clamp (no-op for valid data, prevents OOB fault)
        i = min(max(i, 0), N - 1);
        j = min(max(j, 0), N - 1);

        float4 q0 = g_node[i * 4 + 0];
        float4 q1 = g_node[i * 4 + 1];
        float4 q2 = g_node[i * 4 + 2];

        float cix = cp[3 * i + 0], ciy = cp[3 * i + 1], ciz = cp[3 * i + 2];
        float cjx = cp[3 * j + 0], cjy = cp[3 * j + 1], cjz = cp[3 * j + 2];
        float tix = t[3 * i + 0],  tiy = t[3 * i + 1],  tiz = t[3 * i + 2];
        float tjx = t[3 * j + 0],  tjy = t[3 * j + 1],  tjz = t[3 * j + 2];

        float dx = cjx - cix, dy = cjy - ciy, dz = cjz - ciz;

        float r0 = fmaf(q0.x, dx, fmaf(q0.y, dy, q0.z * dz)) + cix + tix - cjx - tjx;
        float r1 = fmaf(q1.x, dx, fmaf(q1.y, dy, q1.z * dz)) + ciy + tiy - cjy - tjy;
        float r2 = fmaf(q2.x, dx, fmaf(q2.y, dy, q2.z * dz)) + ciz + tiz - cjz - tjz;

        acc += r0 * r0 + r1 * r1 + r2 * r2;
    }

    red[threadIdx.x] = acc;
    __syncthreads();
    for (int s = blockDim.x / 2; s > 0; s >>= 1) {
        if (threadIdx.x < (unsigned)s) red[threadIdx.x] += red[threadIdx.x + s];
        __syncthreads();
    }
    if (threadIdx.x == 0) out[3 * P] = red[0];
}

// ---------------------------------------------------------------------------
// Launch
// ---------------------------------------------------------------------------
extern "C" void kernel_launch(void* const* d_in, const int* in_sizes, int n_in,
                              void* d_out, int out_size) {
    const float* points  = (const float*)d_in[0];
    const float* cp      = (const float*)d_in[1];
    const float* rot_vec = (const float*)d_in[2];
    const float* t       = (const float*)d_in[3];
    const int*   edges   = (const int*)d_in[4];

    float* out = (float*)d_out;

    int P = in_sizes[0] / 3;
    int N = in_sizes[1] / 3;
    int E = in_sizes[4] / 2;
    if (N > MAXN) N = MAXN; // defensive

    // 1. Per-node constants
    prep_kernel<<<(N + 255) / 256, 256>>>(cp, rot_vec, t, N);

    // 2. Main warp field
    int block = 128;
    int grid = (P + block - 1) / block;
    size_t smem = (size_t)N * 4 * sizeof(float4);
    warp_kernel<<<grid, block, smem>>>(points, out, N, P);

    // 3. Edge regularizer (writes out[3*P], deterministic)
    edge_kernel<<<1, 1024>>>(cp, t, edges, out, E, P, N);
}

// round 4
// speedup vs baseline: 1.1974x; 1.1974x over previous
#include <cuda_runtime.h>
#include <cuda_bf16.h>

// ============================================================================
// Single fused kernel.
//  Blocks [0, NPB): point warp field, 2 points/thread via packed f32x2 math.
//  Block  NPB     : edge regularizer (computes its own Rodrigues per edge).
//
// Per node, smem holds 16 replicated float2 slots (128 B):
//   0:r00 1:r01 2:r02 3:u0 4:r10 5:r11 6:r12 7:u1
//   8:r20 9:r21 10:r22 11:u2 12:-cx 13:-cy 14:-cz 15:0
// where u = t + c - R*c, so contribution = w * (R*p + u).
// ============================================================================

#define PTS_PER_THREAD 2
#define BLOCK_THREADS 256
#define PTS_PER_BLOCK (PTS_PER_THREAD * BLOCK_THREADS)

// ---- packed f32x2 helpers (sm_103a) ----------------------------------------
__device__ __forceinline__ unsigned long long pk2(float a, float b) {
    unsigned long long r;
    asm("mov.b64 %0, {%1, %2};" : "=l"(r) : "f"(a), "f"(b));
    return r;
}
__device__ __forceinline__ void upk2(unsigned long long v, float& a, float& b) {
    asm("mov.b64 {%0, %1}, %2;" : "=f"(a), "=f"(b) : "l"(v));
}
__device__ __forceinline__ unsigned long long add2(unsigned long long a, unsigned long long b) {
    unsigned long long r;
    asm("add.rn.f32x2 %0, %1, %2;" : "=l"(r) : "l"(a), "l"(b));
    return r;
}
__device__ __forceinline__ unsigned long long mul2(unsigned long long a, unsigned long long b) {
    unsigned long long r;
    asm("mul.rn.f32x2 %0, %1, %2;" : "=l"(r) : "l"(a), "l"(b));
    return r;
}
__device__ __forceinline__ unsigned long long fma2(unsigned long long a, unsigned long long b,
                                                   unsigned long long c) {
    unsigned long long r;
    asm("fma.rn.f32x2 %0, %1, %2, %3;" : "=l"(r) : "l"(a), "l"(b), "l"(c));
    return r;
}
__device__ __forceinline__ float ex2f(float x) {
    float r;
    asm("ex2.approx.f32 %0, %1;" : "=f"(r) : "f"(x));
    return r;
}

// ---- Rodrigues --------------------------------------------------------------
__device__ __forceinline__ void rodrigues(float x, float y, float z, float R[9]) {
    float th2 = x * x + y * y + z * z + 1e-12f;
    float th = sqrtf(th2);
    float s, co;
    sincosf(th, &s, &co);
    float a = s / th;
    float b = (1.0f - co) / th2;
    float xx = x * x, yy = y * y, zz = z * z;
    float xy = x * y, xz = x * z, yz = y * z;
    R[0] = 1.0f - b * (yy + zz);
    R[1] = -a * z + b * xy;
    R[2] =  a * y + b * xz;
    R[3] =  a * z + b * xy;
    R[4] = 1.0f - b * (xx + zz);
    R[5] = -a * x + b * yz;
    R[6] = -a * y + b * xz;
    R[7] =  a * x + b * yz;
    R[8] = 1.0f - b * (xx + yy);
}

__global__ void __launch_bounds__(BLOCK_THREADS)
fused_kernel(const float* __restrict__ pts,
             const float* __restrict__ cp,
             const float* __restrict__ rv,
             const float* __restrict__ t,
             const int* __restrict__ edges,
             float* __restrict__ out,
             int N, int P, int E, int nPointBlocks) {
    extern __shared__ float2 sf[];  // 16 replicated float2 per node

    // ------------------------------------------------------------------
    // Edge block: last block of the grid
    // ------------------------------------------------------------------
    if (blockIdx.x == (unsigned)nPointBlocks) {
        __shared__ float red[BLOCK_THREADS];
        float acc = 0.0f;
        for (int m = threadIdx.x; m < E; m += BLOCK_THREADS) {
            int i = edges[2 * m + 0];
            int j = edges[2 * m + 1];
            i = min(max(i, 0), N - 1);
            j = min(max(j, 0), N - 1);

            float R[9];
            rodrigues(rv[3 * i + 0], rv[3 * i + 1], rv[3 * i + 2], R);

            float cix = cp[3 * i + 0], ciy = cp[3 * i + 1], ciz = cp[3 * i + 2];
            float cjx = cp[3 * j + 0], cjy = cp[3 * j + 1], cjz = cp[3 * j + 2];
            float tix = t[3 * i + 0],  tiy = t[3 * i + 1],  tiz = t[3 * i + 2];
            float tjx = t[3 * j + 0],  tjy = t[3 * j + 1],  tjz = t[3 * j + 2];

            float dx = cjx - cix, dy = cjy - ciy, dz = cjz - ciz;

            float r0 = fmaf(R[0], dx, fmaf(R[1], dy, R[2] * dz)) + cix + tix - cjx - tjx;
            float r1 = fmaf(R[3], dx, fmaf(R[4], dy, R[5] * dz)) + ciy + tiy - cjy - tjy;
            float r2 = fmaf(R[6], dx, fmaf(R[7], dy, R[8] * dz)) + ciz + tiz - cjz - tjz;

            acc += r0 * r0 + r1 * r1 + r2 * r2;
        }
        red[threadIdx.x] = acc;
        __syncthreads();
        for (int s = BLOCK_THREADS / 2; s > 0; s >>= 1) {
            if (threadIdx.x < (unsigned)s) red[threadIdx.x] += red[threadIdx.x + s];
            __syncthreads();
        }
        if (threadIdx.x == 0) out[3 * P] = red[0];
        return;
    }

    // ------------------------------------------------------------------
    // Point blocks: stage node constants (each block computes Rodrigues)
    // ------------------------------------------------------------------
    for (int n = threadIdx.x; n < N; n += BLOCK_THREADS) {
        float R[9];
        rodrigues(rv[3 * n + 0], rv[3 * n + 1], rv[3 * n + 2], R);
        float cx = cp[3 * n + 0], cy = cp[3 * n + 1], cz = cp[3 * n + 2];
        float tx = t[3 * n + 0],  ty = t[3 * n + 1],  tz = t[3 * n + 2];
        float u0 = tx + cx - (R[0] * cx + R[1] * cy + R[2] * cz);
        float u1 = ty + cy - (R[3] * cx + R[4] * cy + R[5] * cz);
        float u2 = tz + cz - (R[6] * cx + R[7] * cy + R[8] * cz);

        float2* s = sf + 16 * n;
        s[0]  = make_float2(R[0], R[0]);
        s[1]  = make_float2(R[1], R[1]);
        s[2]  = make_float2(R[2], R[2]);
        s[3]  = make_float2(u0, u0);
        s[4]  = make_float2(R[3], R[3]);
        s[5]  = make_float2(R[4], R[4]);
        s[6]  = make_float2(R[5], R[5]);
        s[7]  = make_float2(u1, u1);
        s[8]  = make_float2(R[6], R[6]);
        s[9]  = make_float2(R[7], R[7]);
        s[10] = make_float2(R[8], R[8]);
        s[11] = make_float2(u2, u2);
        s[12] = make_float2(-cx, -cx);
        s[13] = make_float2(-cy, -cy);
        s[14] = make_float2(-cz, -cz);
        s[15] = make_float2(0.0f, 0.0f);
    }
    __syncthreads();

    // ------------------------------------------------------------------
    // Main loop: 2 points per thread, packed f32x2
    // ------------------------------------------------------------------
    int base = blockIdx.x * PTS_PER_BLOCK;
    int pA = base + threadIdx.x;
    int pB = pA + BLOCK_THREADS;
    bool vA = pA < P, vB = pB < P;
    int lA = vA ? pA : 0, lB = vB ? pB : 0;

    unsigned long long px2 = pk2(pts[3 * lA + 0], pts[3 * lB + 0]);
    unsigned long long py2 = pk2(pts[3 * lA + 1], pts[3 * lB + 1]);
    unsigned long long pz2 = pk2(pts[3 * lA + 2], pts[3 * lB + 2]);

    unsigned long long ax = 0ull, ay = 0ull, az = 0ull, S = 0ull;

    const float KEXP2 = -0.02f * 1.44269504f;  // -1/(2*sigma^2) * log2(e)

    const ulonglong2* sm = (const ulonglong2*)sf;

#pragma unroll 4
    for (int n = 0; n < N; ++n) {
        ulonglong2 a0 = sm[8 * n + 0];  // (r00, r01)
        ulonglong2 a1 = sm[8 * n + 1];  // (r02, u0)
        ulonglong2 a2 = sm[8 * n + 2];  // (r10, r11)
        ulonglong2 a3 = sm[8 * n + 3];  // (r12, u1)
        ulonglong2 a4 = sm[8 * n + 4];  // (r20, r21)
        ulonglong2 a5 = sm[8 * n + 5];  // (r22, u2)
        ulonglong2 a6 = sm[8 * n + 6];  // (-cx, -cy)
        ulonglong2 a7 = sm[8 * n + 7];  // (-cz, 0)

        unsigned long long dx = add2(px2, a6.x);
        unsigned long long dy = add2(py2, a6.y);
        unsigned long long dz = add2(pz2, a7.x);
        unsigned long long d2 = mul2(dz, dz);
        d2 = fma2(dy, dy, d2);
        d2 = fma2(dx, dx, d2);

        float d0, d1;
        upk2(d2, d0, d1);
        float w0 = ex2f(d0 * KEXP2);
        float w1 = ex2f(d1 * KEXP2);
        unsigned long long ww = pk2(w0, w1);

        unsigned long long y0 = fma2(a0.x, px2, fma2(a0.y, py2, fma2(a1.x, pz2, a1.y)));
        unsigned long long y1 = fma2(a2.x, px2, fma2(a2.y, py2, fma2(a3.x, pz2, a3.y)));
        unsigned long long y2 = fma2(a4.x, px2, fma2(a4.y, py2, fma2(a5.x, pz2, a5.y)));

        ax = fma2(ww, y0, ax);
        ay = fma2(ww, y1, ay);
        az = fma2(ww, y2, az);
        S = add2(S, ww);
    }

    float axA, axB, ayA, ayB, azA, azB, SA, SB;
    upk2(ax, axA, axB);
    upk2(ay, ayA, ayB);
    upk2(az, azA, azB);
    upk2(S, SA, SB);

    if (vA) {
        float inv = 1.0f / (SA + 1e-5f);
        out[3 * pA + 0] = axA * inv;
        out[3 * pA + 1] = ayA * inv;
        out[3 * pA + 2] = azA * inv;
    }
    if (vB) {
        float inv = 1.0f / (SB + 1e-5f);
        out[3 * pB + 0] = axB * inv;
        out[3 * pB + 1] = ayB * inv;
        out[3 * pB + 2] = azB * inv;
    }
}

// ---------------------------------------------------------------------------
extern "C" void kernel_launch(void* const* d_in, const int* in_sizes, int n_in,
                              void* d_out, int out_size) {
    const float* points  = (const float*)d_in[0];
    const float* cp      = (const float*)d_in[1];
    const float* rot_vec = (const float*)d_in[2];
    const float* t       = (const float*)d_in[3];
    const int*   edges   = (const int*)d_in[4];

    float* out = (float*)d_out;

    int P = in_sizes[0] / 3;
    int N = in_sizes[1] / 3;
    int E = in_sizes[4] / 2;

    int nPointBlocks = (P + PTS_PER_BLOCK - 1) / PTS_PER_BLOCK;
    size_t smem = (size_t)N * 16 * sizeof(float2);  // 128 B per node

    cudaFuncSetAttribute(fused_kernel,
                         cudaFuncAttributeMaxDynamicSharedMemorySize,
                         (int)smem);

    fused_kernel<<<nPointBlocks + 1, BLOCK_THREADS, smem>>>(
        points, cp, rot_vec, t, edges, out, N, P, E, nPointBlocks);
}

// round 5
// speedup vs baseline: 1.4376x; 1.2006x over previous
#include <cuda_runtime.h>
#include <cuda_bf16.h>

// ============================================================================
// Grid = nTiles*NSPLIT point-blocks + 1 edge-block, then a combine kernel.
// Each point-block: 512 points x 128 nodes (N/4), partial sums to scratch.
// f32x2 packed math, 2 points/thread, node constants replicated in smem.
//
// smem per node: 16 replicated float2 slots (128 B):
//   0:r00 1:r01 2:r02 3:u0  4:r10 5:r11 6:r12 7:u1
//   8:r20 9:r21 10:r22 11:u2 12:-cx*SS 13:-cy*SS 14:-cz*SS 15:0
// u = t + c - R*c  (contribution = w * (R*p + u));
// SS = sqrt(log2(e)/(2*sigma^2)) so w = ex2(-(dx'^2+dy'^2+dz'^2)).
// ============================================================================

#define BLOCK_THREADS 256
#define PTS_PER_BLOCK 512      // 2 points per thread
#define NSPLIT 4
#define MAXP 65536

__device__ float4 g_part[NSPLIT * MAXP];   // (ax, ay, az, S) partials, 4 MB

// ---- packed f32x2 helpers (sm_103a) ----------------------------------------
__device__ __forceinline__ unsigned long long pk2(float a, float b) {
    unsigned long long r;
    asm("mov.b64 %0, {%1, %2};" : "=l"(r) : "f"(a), "f"(b));
    return r;
}
__device__ __forceinline__ void upk2(unsigned long long v, float& a, float& b) {
    asm("mov.b64 {%0, %1}, %2;" : "=f"(a), "=f"(b) : "l"(v));
}
__device__ __forceinline__ unsigned long long add2(unsigned long long a, unsigned long long b) {
    unsigned long long r;
    asm("add.rn.f32x2 %0, %1, %2;" : "=l"(r) : "l"(a), "l"(b));
    return r;
}
__device__ __forceinline__ unsigned long long mul2(unsigned long long a, unsigned long long b) {
    unsigned long long r;
    asm("mul.rn.f32x2 %0, %1, %2;" : "=l"(r) : "l"(a), "l"(b));
    return r;
}
__device__ __forceinline__ unsigned long long fma2(unsigned long long a, unsigned long long b,
                                                   unsigned long long c) {
    unsigned long long r;
    asm("fma.rn.f32x2 %0, %1, %2, %3;" : "=l"(r) : "l"(a), "l"(b), "l"(c));
    return r;
}
__device__ __forceinline__ float ex2f(float x) {
    float r;
    asm("ex2.approx.f32 %0, %1;" : "=f"(r) : "f"(x));
    return r;
}

// ---- Rodrigues --------------------------------------------------------------
__device__ __forceinline__ void rodrigues(float x, float y, float z, float R[9]) {
    float th2 = x * x + y * y + z * z + 1e-12f;
    float th = sqrtf(th2);
    float s, co;
    sincosf(th, &s, &co);
    float a = s / th;
    float b = (1.0f - co) / th2;
    float xx = x * x, yy = y * y, zz = z * z;
    float xy = x * y, xz = x * z, yz = y * z;
    R[0] = 1.0f - b * (yy + zz);
    R[1] = -a * z + b * xy;
    R[2] =  a * y + b * xz;
    R[3] =  a * z + b * xy;
    R[4] = 1.0f - b * (xx + zz);
    R[5] = -a * x + b * yz;
    R[6] = -a * y + b * xz;
    R[7] =  a * x + b * yz;
    R[8] = 1.0f - b * (xx + yy);
}

// SS^2 = (1/(2*sigma^2)) * log2(e) = 0.02 * 1.44269504
#define SSCALE 0.1698643394f

__global__ void __launch_bounds__(BLOCK_THREADS)
main_kernel(const float* __restrict__ pts,
            const float* __restrict__ cp,
            const float* __restrict__ rv,
            const float* __restrict__ t,
            const int* __restrict__ edges,
            float* __restrict__ out,
            int N, int P, int E, int nTiles, int chunk) {
    extern __shared__ float2 sf[];  // 16 replicated float2 per local node

    // ------------------------------------------------------------------
    // Edge block (last block)
    // ------------------------------------------------------------------
    if (blockIdx.x == (unsigned)(nTiles * NSPLIT)) {
        __shared__ float red[BLOCK_THREADS];
        float acc = 0.0f;
        for (int m = threadIdx.x; m < E; m += BLOCK_THREADS) {
            int i = edges[2 * m + 0];
            int j = edges[2 * m + 1];
            i = min(max(i, 0), N - 1);
            j = min(max(j, 0), N - 1);

            float R[9];
            rodrigues(rv[3 * i + 0], rv[3 * i + 1], rv[3 * i + 2], R);

            float cix = cp[3 * i + 0], ciy = cp[3 * i + 1], ciz = cp[3 * i + 2];
            float cjx = cp[3 * j + 0], cjy = cp[3 * j + 1], cjz = cp[3 * j + 2];
            float tix = t[3 * i + 0],  tiy = t[3 * i + 1],  tiz = t[3 * i + 2];
            float tjx = t[3 * j + 0],  tjy = t[3 * j + 1],  tjz = t[3 * j + 2];

            float dx = cjx - cix, dy = cjy - ciy, dz = cjz - ciz;

            float r0 = fmaf(R[0], dx, fmaf(R[1], dy, R[2] * dz)) + cix + tix - cjx - tjx;
            float r1 = fmaf(R[3], dx, fmaf(R[4], dy, R[5] * dz)) + ciy + tiy - cjy - tjy;
            float r2 = fmaf(R[6], dx, fmaf(R[7], dy, R[8] * dz)) + ciz + tiz - cjz - tjz;

            acc += r0 * r0 + r1 * r1 + r2 * r2;
        }
        red[threadIdx.x] = acc;
        __syncthreads();
        for (int s = BLOCK_THREADS / 2; s > 0; s >>= 1) {
            if (threadIdx.x < (unsigned)s) red[threadIdx.x] += red[threadIdx.x + s];
            __syncthreads();
        }
        if (threadIdx.x == 0) out[3 * P] = red[0];
        return;
    }

    int split = blockIdx.x / nTiles;
    int tile  = blockIdx.x % nTiles;
    int n0 = split * chunk;
    int nNodes = min(chunk, N - n0);
    if (nNodes < 0) nNodes = 0;

    // ------------------------------------------------------------------
    // Stage this split's node constants (compute Rodrigues in-block)
    // ------------------------------------------------------------------
    for (int ln = threadIdx.x; ln < nNodes; ln += BLOCK_THREADS) {
        int n = n0 + ln;
        float R[9];
        rodrigues(rv[3 * n + 0], rv[3 * n + 1], rv[3 * n + 2], R);
        float cx = cp[3 * n + 0], cy = cp[3 * n + 1], cz = cp[3 * n + 2];
        float tx = t[3 * n + 0],  ty = t[3 * n + 1],  tz = t[3 * n + 2];
        float u0 = tx + cx - (R[0] * cx + R[1] * cy + R[2] * cz);
        float u1 = ty + cy - (R[3] * cx + R[4] * cy + R[5] * cz);
        float u2 = tz + cz - (R[6] * cx + R[7] * cy + R[8] * cz);

        float2* s = sf + 16 * ln;
        s[0]  = make_float2(R[0], R[0]);
        s[1]  = make_float2(R[1], R[1]);
        s[2]  = make_float2(R[2], R[2]);
        s[3]  = make_float2(u0, u0);
        s[4]  = make_float2(R[3], R[3]);
        s[5]  = make_float2(R[4], R[4]);
        s[6]  = make_float2(R[5], R[5]);
        s[7]  = make_float2(u1, u1);
        s[8]  = make_float2(R[6], R[6]);
        s[9]  = make_float2(R[7], R[7]);
        s[10] = make_float2(R[8], R[8]);
        s[11] = make_float2(u2, u2);
        s[12] = make_float2(-cx * SSCALE, -cx * SSCALE);
        s[13] = make_float2(-cy * SSCALE, -cy * SSCALE);
        s[14] = make_float2(-cz * SSCALE, -cz * SSCALE);
        s[15] = make_float2(0.0f, 0.0f);
    }
    __syncthreads();

    // ------------------------------------------------------------------
    // 2 points per thread, packed f32x2, partial accumulation
    // ------------------------------------------------------------------
    int base = tile * PTS_PER_BLOCK;
    int pA = base + threadIdx.x;
    int pB = pA + BLOCK_THREADS;
    bool vA = pA < P, vB = pB < P;
    int lA = vA ? pA : 0, lB = vB ? pB : 0;

    float pxA = pts[3 * lA + 0], pxB = pts[3 * lB + 0];
    float pyA = pts[3 * lA + 1], pyB = pts[3 * lB + 1];
    float pzA = pts[3 * lA + 2], pzB = pts[3 * lB + 2];

    unsigned long long px2 = pk2(pxA, pxB);
    unsigned long long py2 = pk2(pyA, pyB);
    unsigned long long pz2 = pk2(pzA, pzB);
    // pre-scaled coords for the Gaussian argument
    unsigned long long sx2 = pk2(pxA * SSCALE, pxB * SSCALE);
    unsigned long long sy2 = pk2(pyA * SSCALE, pyB * SSCALE);
    unsigned long long sz2 = pk2(pzA * SSCALE, pzB * SSCALE);

    unsigned long long ax = 0ull, ay = 0ull, az = 0ull, S = 0ull;

    const ulonglong2* sm = (const ulonglong2*)sf;

#pragma unroll 4
    for (int n = 0; n < nNodes; ++n) {
        ulonglong2 a0 = sm[8 * n + 0];  // (r00, r01)
        ulonglong2 a1 = sm[8 * n + 1];  // (r02, u0)
        ulonglong2 a2 = sm[8 * n + 2];  // (r10, r11)
        ulonglong2 a3 = sm[8 * n + 3];  // (r12, u1)
        ulonglong2 a4 = sm[8 * n + 4];  // (r20, r21)
        ulonglong2 a5 = sm[8 * n + 5];  // (r22, u2)
        ulonglong2 a6 = sm[8 * n + 6];  // (-cx*SS, -cy*SS)
        ulonglong2 a7 = sm[8 * n + 7];  // (-cz*SS, 0)

        unsigned long long dx = add2(sx2, a6.x);
        unsigned long long dy = add2(sy2, a6.y);
        unsigned long long dz = add2(sz2, a7.x);
        unsigned long long d2 = mul2(dz, dz);
        d2 = fma2(dy, dy, d2);
        d2 = fma2(dx, dx, d2);

        float d0, d1;
        upk2(d2, d0, d1);
        float w0 = ex2f(-d0);
        float w1 = ex2f(-d1);
        unsigned long long ww = pk2(w0, w1);

        unsigned long long y0 = fma2(a0.x, px2, fma2(a0.y, py2, fma2(a1.x, pz2, a1.y)));
        unsigned long long y1 = fma2(a2.x, px2, fma2(a2.y, py2, fma2(a3.x, pz2, a3.y)));
        unsigned long long y2 = fma2(a4.x, px2, fma2(a4.y, py2, fma2(a5.x, pz2, a5.y)));

        ax = fma2(ww, y0, ax);
        ay = fma2(ww, y1, ay);
        az = fma2(ww, y2, az);
        S = add2(S, ww);
    }

    float axA, axB, ayA, ayB, azA, azB, SA, SB;
    upk2(ax, axA, axB);
    upk2(ay, ayA, ayB);
    upk2(az, azA, azB);
    upk2(S, SA, SB);

    if (vA) g_part[split * P + pA] = make_float4(axA, ayA, azA, SA);
    if (vB) g_part[split * P + pB] = make_float4(axB, ayB, azB, SB);
}

// ---------------------------------------------------------------------------
// Combine: sum NSPLIT partials per point, normalize, write output.
// ---------------------------------------------------------------------------
__global__ void __launch_bounds__(256)
combine_kernel(float* __restrict__ out, int P) {
    int p = blockIdx.x * blockDim.x + threadIdx.x;
    if (p >= P) return;
    float ax = 0.0f, ay = 0.0f, az = 0.0f, S = 0.0f;
#pragma unroll
    for (int s = 0; s < NSPLIT; ++s) {
        float4 v = g_part[s * P + p];
        ax += v.x; ay += v.y; az += v.z; S += v.w;
    }
    float inv = 1.0f / (S + 1e-5f);
    out[3 * p + 0] = ax * inv;
    out[3 * p + 1] = ay * inv;
    out[3 * p + 2] = az * inv;
}

// ---------------------------------------------------------------------------
extern "C" void kernel_launch(void* const* d_in, const int* in_sizes, int n_in,
                              void* d_out, int out_size) {
    const float* points  = (const float*)d_in[0];
    const float* cp      = (const float*)d_in[1];
    const float* rot_vec = (const float*)d_in[2];
    const float* t       = (const float*)d_in[3];
    const int*   edges   = (const int*)d_in[4];

    float* out = (float*)d_out;

    int P = in_sizes[0] / 3;
    if (P > MAXP) P = MAXP;  // defensive (scratch bound)
    int N = in_sizes[1] / 3;
    int E = in_sizes[4] / 2;

    int nTiles = (P + PTS_PER_BLOCK - 1) / PTS_PER_BLOCK;
    int chunk = (N + NSPLIT - 1) / NSPLIT;
    size_t smem = (size_t)chunk * 16 * sizeof(float2);  // 128 B per node

    main_kernel<<<nTiles * NSPLIT + 1, BLOCK_THREADS, smem>>>(
        points, cp, rot_vec, t, edges, out, N, P, E, nTiles, chunk);

    combine_kernel<<<(P + 255) / 256, 256>>>(out, P);
}